// round 1
// baseline (speedup 1.0000x reference)
#include <cuda_runtime.h>
#include <cuda_bf16.h>
#include <cstdint>

#define BATCH 32768
#define HD 512
typedef __nv_bfloat16 bf16;

// ---------------- device scratch (no allocations allowed) ----------------
__device__ bf16 g_x_hi[BATCH * HD];
__device__ bf16 g_x_lo[BATCH * HD];
__device__ bf16 g_u_hi[BATCH * HD];
__device__ bf16 g_u_lo[BATCH * HD];
__device__ bf16 g_t_hi[BATCH * HD];
__device__ bf16 g_t_lo[BATCH * HD];
__device__ float g_pre[BATCH * HD];               // GEMM1 out, reused for GEMM3 out
__device__ float g_P[(size_t)BATCH * 4 * HD];     // z_pre | k | v | d_pre
__device__ float g_z[BATCH * HD];
__device__ bf16 g_Wt_in_hi[HD * HD], g_Wt_in_lo[HD * HD];
__device__ bf16 g_Wt_cat_hi[4 * HD * HD], g_Wt_cat_lo[4 * HD * HD];
__device__ bf16 g_Wt_h_hi[HD * HD], g_Wt_h_lo[HD * HD];

// ---------------- helpers ----------------
__device__ __forceinline__ uint32_t smem_u32(const void* p) {
    return (uint32_t)__cvta_generic_to_shared(p);
}
__device__ __forceinline__ void cp16(uint32_t dst, const void* src) {
    asm volatile("cp.async.cg.shared.global [%0], [%1], 16;\n" :: "r"(dst), "l"(src));
}
__device__ __forceinline__ void ldm4(uint32_t (&r)[4], uint32_t addr) {
    asm volatile("ldmatrix.sync.aligned.m8n8.x4.shared.b16 {%0,%1,%2,%3}, [%4];\n"
                 : "=r"(r[0]), "=r"(r[1]), "=r"(r[2]), "=r"(r[3]) : "r"(addr));
}
__device__ __forceinline__ void mma16816(float (&d)[4], const uint32_t (&a)[4],
                                         uint32_t b0, uint32_t b1) {
    asm volatile("mma.sync.aligned.m16n8k16.row.col.f32.bf16.bf16.f32 "
                 "{%0,%1,%2,%3}, {%4,%5,%6,%7}, {%8,%9}, {%0,%1,%2,%3};\n"
                 : "+f"(d[0]), "+f"(d[1]), "+f"(d[2]), "+f"(d[3])
                 : "r"(a[0]), "r"(a[1]), "r"(a[2]), "r"(a[3]), "r"(b0), "r"(b1));
}
__device__ __forceinline__ float sigf(float x) { return 1.0f / (1.0f + __expf(-x)); }

__device__ __forceinline__ void split_store2(bf16* hi, bf16* lo, float a, float b) {
    bf16 ha = __float2bfloat16(a);
    bf16 hb = __float2bfloat16(b);
    *reinterpret_cast<__nv_bfloat162*>(hi) = __halves2bfloat162(ha, hb);
    bf16 la = __float2bfloat16(a - __bfloat162float(ha));
    bf16 lb = __float2bfloat16(b - __bfloat162float(hb));
    *reinterpret_cast<__nv_bfloat162*>(lo) = __halves2bfloat162(la, lb);
}

// ---------------- weight prep: transpose + bf16 split ----------------
__global__ void prep_weights(const float* __restrict__ W_in, const float* __restrict__ W_z,
                             const float* __restrict__ W_k, const float* __restrict__ W_v,
                             const float* __restrict__ W_d, const float* __restrict__ W_h) {
    int idx = blockIdx.x * 256 + threadIdx.x;
    if (idx >= 6 * HD * HD) return;
    int mat = idx / (HD * HD);
    int e = idx % (HD * HD);
    int k = e / HD, n = e % HD;
    const float* W;
    bf16 *hi, *lo;
    int dst;
    if (mat == 0) {
        W = W_in; hi = g_Wt_in_hi; lo = g_Wt_in_lo; dst = n * HD + k;
    } else if (mat <= 4) {
        W = (mat == 1) ? W_z : (mat == 2) ? W_k : (mat == 3) ? W_v : W_d;
        hi = g_Wt_cat_hi; lo = g_Wt_cat_lo; dst = ((mat - 1) * HD + n) * HD + k;
    } else {
        W = W_h; hi = g_Wt_h_hi; lo = g_Wt_h_lo; dst = n * HD + k;
    }
    float w = W[e];  // W[k][n], coalesced over n
    bf16 h = __float2bfloat16(w);
    hi[dst] = h;
    lo[dst] = __float2bfloat16(w - __bfloat162float(h));
}

// ---------------- split x into bf16 hi/lo ----------------
__global__ void split_x_kernel(const float* __restrict__ x) {
    int i = blockIdx.x * 256 + threadIdx.x;  // over BATCH*HD/4 float4s
    float4 v = reinterpret_cast<const float4*>(x)[i];
    size_t idx = (size_t)i * 4;
    split_store2(g_x_hi + idx, g_x_lo + idx, v.x, v.y);
    split_store2(g_x_hi + idx + 2, g_x_lo + idx + 2, v.z, v.w);
}

// ---------------- split-bf16 GEMM: C[M,N] = A[M,512] @ W[512,N] ----------------
// 3-term: Ahi*Bhi + Alo*Bhi + Ahi*Blo  (K loop runs 3x512)
#define BM 128
#define BN 128
#define BK 32
#define KST 40  // padded row stride (bf16 elems) = 80 bytes, 16B-multiple, conflict-free

template <int WHICH>
__global__ void __launch_bounds__(256, 2) gemm3_kernel() {
    const bf16* Ahi = (WHICH == 0) ? g_x_hi : (WHICH == 1) ? g_u_hi : g_t_hi;
    const bf16* Alo = (WHICH == 0) ? g_x_lo : (WHICH == 1) ? g_u_lo : g_t_lo;
    const bf16* Bhi = (WHICH == 0) ? g_Wt_in_hi : (WHICH == 1) ? g_Wt_cat_hi : g_Wt_h_hi;
    const bf16* Blo = (WHICH == 0) ? g_Wt_in_lo : (WHICH == 1) ? g_Wt_cat_lo : g_Wt_h_lo;
    float* C = (WHICH == 1) ? g_P : g_pre;
    const int N = (WHICH == 1) ? 4 * HD : HD;

    __shared__ __align__(16) bf16 As[2][BM][KST];
    __shared__ __align__(16) bf16 Bs[2][BN][KST];

    const int tid = threadIdx.x;
    const int m0 = blockIdx.y * BM;
    const int n0 = blockIdx.x * BN;
    const int warp = tid >> 5, lane = tid & 31;
    const int wm = (warp >> 1) * 32;  // 4 warps along M
    const int wn = (warp & 1) * 64;   // 2 warps along N

    float acc[2][8][4];
#pragma unroll
    for (int i = 0; i < 2; i++)
#pragma unroll
        for (int j = 0; j < 8; j++)
#pragma unroll
            for (int q = 0; q < 4; q++) acc[i][j][q] = 0.f;

    const int ldr = tid >> 2;         // 0..63
    const int ldc = (tid & 3) * 8;    // bf16 col offset (16B chunk)

    auto load_stage = [&](int s, int step) {
        int term = step >> 4;
        int k0 = (step & 15) * BK;
        const bf16* Ag = (term == 1) ? Alo : Ahi;
        const bf16* Bg = (term == 2) ? Blo : Bhi;
        const bf16* ap = Ag + (size_t)(m0 + ldr) * HD + k0 + ldc;
        cp16(smem_u32(&As[s][ldr][ldc]), ap);
        cp16(smem_u32(&As[s][ldr + 64][ldc]), ap + (size_t)64 * HD);
        const bf16* bp = Bg + (size_t)(n0 + ldr) * HD + k0 + ldc;
        cp16(smem_u32(&Bs[s][ldr][ldc]), bp);
        cp16(smem_u32(&Bs[s][ldr + 64][ldc]), bp + (size_t)64 * HD);
    };

    auto compute_stage = [&](int s) {
#pragma unroll
        for (int kk = 0; kk < BK; kk += 16) {
            uint32_t aF[2][4];
#pragma unroll
            for (int mi = 0; mi < 2; mi++) {
                uint32_t ad = smem_u32(&As[s][wm + mi * 16 + (lane & 15)]
                                         [kk + ((lane >> 4) << 3)]);
                ldm4(aF[mi], ad);
            }
            uint32_t bF[4][4];
#pragma unroll
            for (int nb = 0; nb < 4; nb++) {
                uint32_t bd = smem_u32(&Bs[s][wn + nb * 16 + (lane & 7) + ((lane >> 4) << 3)]
                                         [kk + (((lane >> 3) & 1) << 3)]);
                ldm4(bF[nb], bd);
            }
#pragma unroll
            for (int mi = 0; mi < 2; mi++)
#pragma unroll
                for (int ni = 0; ni < 8; ni++)
                    mma16816(acc[mi][ni], aF[mi], bF[ni >> 1][(ni & 1) * 2],
                             bF[ni >> 1][(ni & 1) * 2 + 1]);
        }
    };

    const int NSTEP = 48;  // 3 terms * (512/32)
    load_stage(0, 0);
    asm volatile("cp.async.commit_group;\n");
    for (int step = 0; step < NSTEP; ++step) {
        int cur = step & 1;
        if (step + 1 < NSTEP) load_stage(cur ^ 1, step + 1);
        asm volatile("cp.async.commit_group;\n");
        asm volatile("cp.async.wait_group 1;\n");
        __syncthreads();
        compute_stage(cur);
        __syncthreads();
    }

    // epilogue: write fp32 C
#pragma unroll
    for (int mi = 0; mi < 2; mi++)
#pragma unroll
        for (int ni = 0; ni < 8; ni++) {
            int r = m0 + wm + mi * 16 + (lane >> 2);
            int c = n0 + wn + ni * 8 + (lane & 3) * 2;
            *reinterpret_cast<float2*>(&C[(size_t)r * N + c]) =
                make_float2(acc[mi][ni][0], acc[mi][ni][1]);
            *reinterpret_cast<float2*>(&C[(size_t)(r + 8) * N + c]) =
                make_float2(acc[mi][ni][2], acc[mi][ni][3]);
        }
}

// ---------------- LN over g_pre -> u (bf16 hi/lo) ----------------
__global__ void ln_u_kernel(const float* __restrict__ bias, const float* __restrict__ gamma,
                            const float* __restrict__ beta) {
    int row = blockIdx.x * 8 + (threadIdx.x >> 5);
    int lane = threadIdx.x & 31;
    const float* p = g_pre + (size_t)row * HD;
    float v[16];
    float sm = 0.f, sq = 0.f;
#pragma unroll
    for (int i = 0; i < 4; i++) {
        int c = i * 128 + lane * 4;
        float4 x4 = *reinterpret_cast<const float4*>(p + c);
        float4 b4 = *reinterpret_cast<const float4*>(bias + c);
        float t0 = x4.x + b4.x, t1 = x4.y + b4.y, t2 = x4.z + b4.z, t3 = x4.w + b4.w;
        v[i * 4 + 0] = t0; v[i * 4 + 1] = t1; v[i * 4 + 2] = t2; v[i * 4 + 3] = t3;
        sm += t0 + t1 + t2 + t3;
        sq += t0 * t0 + t1 * t1 + t2 * t2 + t3 * t3;
    }
#pragma unroll
    for (int o = 16; o; o >>= 1) {
        sm += __shfl_xor_sync(0xffffffffu, sm, o);
        sq += __shfl_xor_sync(0xffffffffu, sq, o);
    }
    float mean = sm * (1.f / HD);
    float inv = rsqrtf(fmaxf(sq * (1.f / HD) - mean * mean, 0.f) + 1e-5f);
#pragma unroll
    for (int i = 0; i < 4; i++) {
        int c = i * 128 + lane * 4;
        float4 g4 = *reinterpret_cast<const float4*>(gamma + c);
        float4 b4 = *reinterpret_cast<const float4*>(beta + c);
        float u0 = (v[i * 4 + 0] - mean) * inv * g4.x + b4.x;
        float u1 = (v[i * 4 + 1] - mean) * inv * g4.y + b4.y;
        float u2 = (v[i * 4 + 2] - mean) * inv * g4.z + b4.z;
        float u3 = (v[i * 4 + 3] - mean) * inv * g4.w + b4.w;
        size_t idx = (size_t)row * HD + c;
        split_store2(g_u_hi + idx, g_u_lo + idx, u0, u1);
        split_store2(g_u_hi + idx + 2, g_u_lo + idx + 2, u2, u3);
    }
}

// ---------------- epilogue 1: z, s, t ----------------
__global__ void epi1_kernel(const float* __restrict__ s_prev, const float* __restrict__ bz,
                            const float* __restrict__ glz, const float* __restrict__ blz,
                            const float* __restrict__ bk, const float* __restrict__ bv,
                            const float* __restrict__ bd, float* __restrict__ out_s) {
    int row = blockIdx.x * 8 + (threadIdx.x >> 5);
    int lane = threadIdx.x & 31;
    const float* Pr = g_P + (size_t)row * (4 * HD);
    float zp[16];
    float sm = 0.f, sq = 0.f;
#pragma unroll
    for (int i = 0; i < 4; i++) {
        int c = i * 128 + lane * 4;
        float4 z4 = *reinterpret_cast<const float4*>(Pr + c);
        float4 b4 = *reinterpret_cast<const float4*>(bz + c);
        float t0 = z4.x + b4.x, t1 = z4.y + b4.y, t2 = z4.z + b4.z, t3 = z4.w + b4.w;
        zp[i * 4 + 0] = t0; zp[i * 4 + 1] = t1; zp[i * 4 + 2] = t2; zp[i * 4 + 3] = t3;
        sm += t0 + t1 + t2 + t3;
        sq += t0 * t0 + t1 * t1 + t2 * t2 + t3 * t3;
    }
#pragma unroll
    for (int o = 16; o; o >>= 1) {
        sm += __shfl_xor_sync(0xffffffffu, sm, o);
        sq += __shfl_xor_sync(0xffffffffu, sq, o);
    }
    float mean = sm * (1.f / HD);
    float inv = rsqrtf(fmaxf(sq * (1.f / HD) - mean * mean, 0.f) + 1e-5f);
#pragma unroll
    for (int i = 0; i < 4; i++) {
        int c = i * 128 + lane * 4;
        size_t idx = (size_t)row * HD + c;
        float4 g4 = *reinterpret_cast<const float4*>(glz + c);
        float4 bb4 = *reinterpret_cast<const float4*>(blz + c);
        float z0 = sigf((zp[i * 4 + 0] - mean) * inv * g4.x + bb4.x);
        float z1 = sigf((zp[i * 4 + 1] - mean) * inv * g4.y + bb4.y);
        float z2 = sigf((zp[i * 4 + 2] - mean) * inv * g4.z + bb4.z);
        float z3 = sigf((zp[i * 4 + 3] - mean) * inv * g4.w + bb4.w);

        float4 k4 = *reinterpret_cast<const float4*>(Pr + HD + c);
        float4 bk4 = *reinterpret_cast<const float4*>(bk + c);
        float4 v4 = *reinterpret_cast<const float4*>(Pr + 2 * HD + c);
        float4 bv4 = *reinterpret_cast<const float4*>(bv + c);
        float4 d4 = *reinterpret_cast<const float4*>(Pr + 3 * HD + c);
        float4 bd4 = *reinterpret_cast<const float4*>(bd + c);
        float4 sp = *reinterpret_cast<const float4*>(s_prev + idx);

        float kk0 = k4.x + bk4.x, kk1 = k4.y + bk4.y, kk2 = k4.z + bk4.z, kk3 = k4.w + bk4.w;
        float vv0 = v4.x + bv4.x, vv1 = v4.y + bv4.y, vv2 = v4.z + bv4.z, vv3 = v4.w + bv4.w;
        float dc0 = sigf(d4.x + bd4.x), dc1 = sigf(d4.y + bd4.y);
        float dc2 = sigf(d4.z + bd4.z), dc3 = sigf(d4.w + bd4.w);
        float s0 = dc0 * sp.x + kk0 * vv0;
        float s1 = dc1 * sp.y + kk1 * vv1;
        float s2 = dc2 * sp.z + kk2 * vv2;
        float s3 = dc3 * sp.w + kk3 * vv3;
        *reinterpret_cast<float4*>(out_s + idx) = make_float4(s0, s1, s2, s3);

        __nv_bfloat162 uh0 = *reinterpret_cast<const __nv_bfloat162*>(g_u_hi + idx);
        __nv_bfloat162 ul0 = *reinterpret_cast<const __nv_bfloat162*>(g_u_lo + idx);
        __nv_bfloat162 uh1 = *reinterpret_cast<const __nv_bfloat162*>(g_u_hi + idx + 2);
        __nv_bfloat162 ul1 = *reinterpret_cast<const __nv_bfloat162*>(g_u_lo + idx + 2);
        float u0 = __bfloat162float(uh0.x) + __bfloat162float(ul0.x);
        float u1 = __bfloat162float(uh0.y) + __bfloat162float(ul0.y);
        float u2 = __bfloat162float(uh1.x) + __bfloat162float(ul1.x);
        float u3 = __bfloat162float(uh1.y) + __bfloat162float(ul1.y);
        split_store2(g_t_hi + idx, g_t_lo + idx, u0 + s0, u1 + s1);
        split_store2(g_t_hi + idx + 2, g_t_lo + idx + 2, u2 + s2, u3 + s3);
        *reinterpret_cast<float4*>(g_z + idx) = make_float4(z0, z1, z2, z3);
    }
}

// ---------------- epilogue 2: h ----------------
__global__ void epi2_kernel(const float* __restrict__ h_prev, const float* __restrict__ bh,
                            const float* __restrict__ glh, const float* __restrict__ blh,
                            float* __restrict__ out_h) {
    int row = blockIdx.x * 8 + (threadIdx.x >> 5);
    int lane = threadIdx.x & 31;
    const float* p = g_pre + (size_t)row * HD;
    float v[16];
    float sm = 0.f, sq = 0.f;
#pragma unroll
    for (int i = 0; i < 4; i++) {
        int c = i * 128 + lane * 4;
        float4 x4 = *reinterpret_cast<const float4*>(p + c);
        float4 b4 = *reinterpret_cast<const float4*>(bh + c);
        float t0 = x4.x + b4.x, t1 = x4.y + b4.y, t2 = x4.z + b4.z, t3 = x4.w + b4.w;
        v[i * 4 + 0] = t0; v[i * 4 + 1] = t1; v[i * 4 + 2] = t2; v[i * 4 + 3] = t3;
        sm += t0 + t1 + t2 + t3;
        sq += t0 * t0 + t1 * t1 + t2 * t2 + t3 * t3;
    }
#pragma unroll
    for (int o = 16; o; o >>= 1) {
        sm += __shfl_xor_sync(0xffffffffu, sm, o);
        sq += __shfl_xor_sync(0xffffffffu, sq, o);
    }
    float mean = sm * (1.f / HD);
    float inv = rsqrtf(fmaxf(sq * (1.f / HD) - mean * mean, 0.f) + 1e-5f);
#pragma unroll
    for (int i = 0; i < 4; i++) {
        int c = i * 128 + lane * 4;
        size_t idx = (size_t)row * HD + c;
        float4 g4 = *reinterpret_cast<const float4*>(glh + c);
        float4 b4 = *reinterpret_cast<const float4*>(blh + c);
        float c0 = tanhf((v[i * 4 + 0] - mean) * inv * g4.x + b4.x);
        float c1 = tanhf((v[i * 4 + 1] - mean) * inv * g4.y + b4.y);
        float c2 = tanhf((v[i * 4 + 2] - mean) * inv * g4.z + b4.z);
        float c3 = tanhf((v[i * 4 + 3] - mean) * inv * g4.w + b4.w);
        float4 z4 = *reinterpret_cast<const float4*>(g_z + idx);
        float4 hp = *reinterpret_cast<const float4*>(h_prev + idx);
        float h0 = (1.f - z4.x) * c0 + z4.x * hp.x;
        float h1 = (1.f - z4.y) * c1 + z4.y * hp.y;
        float h2 = (1.f - z4.z) * c2 + z4.z * hp.z;
        float h3 = (1.f - z4.w) * c3 + z4.w * hp.w;
        *reinterpret_cast<float4*>(out_h + idx) = make_float4(h0, h1, h2, h3);
    }
}

// ---------------- launch ----------------
extern "C" void kernel_launch(void* const* d_in, const int* in_sizes, int n_in,
                              void* d_out, int out_size) {
    const float* x       = (const float*)d_in[0];
    const float* h_prev  = (const float*)d_in[1];
    const float* s_prev  = (const float*)d_in[2];
    const float* W_in    = (const float*)d_in[3];
    const float* b_in    = (const float*)d_in[4];
    const float* g_ln_in = (const float*)d_in[5];
    const float* b_ln_in = (const float*)d_in[6];
    // d_in[7], d_in[8]: g_ln_r, b_ln_r (r is unused downstream)
    const float* g_ln_z  = (const float*)d_in[9];
    const float* b_ln_z  = (const float*)d_in[10];
    const float* g_ln_h  = (const float*)d_in[11];
    const float* b_ln_h  = (const float*)d_in[12];
    // d_in[13], d_in[14]: W_r, b_r (unused)
    const float* W_z     = (const float*)d_in[15];
    const float* b_z     = (const float*)d_in[16];
    const float* W_k     = (const float*)d_in[17];
    const float* b_k     = (const float*)d_in[18];
    const float* W_v     = (const float*)d_in[19];
    const float* b_v     = (const float*)d_in[20];
    const float* W_h     = (const float*)d_in[21];
    const float* b_h     = (const float*)d_in[22];
    const float* W_d     = (const float*)d_in[23];
    const float* b_d     = (const float*)d_in[24];

    float* out_h = (float*)d_out;
    float* out_s = out_h + (size_t)BATCH * HD;

    prep_weights<<<(6 * HD * HD + 255) / 256, 256>>>(W_in, W_z, W_k, W_v, W_d, W_h);
    split_x_kernel<<<BATCH * HD / 4 / 256, 256>>>(x);

    gemm3_kernel<0><<<dim3(HD / BN, BATCH / BM), 256>>>();
    ln_u_kernel<<<BATCH / 8, 256>>>(b_in, g_ln_in, b_ln_in);

    gemm3_kernel<1><<<dim3(4 * HD / BN, BATCH / BM), 256>>>();
    epi1_kernel<<<BATCH / 8, 256>>>(s_prev, b_z, g_ln_z, b_ln_z, b_k, b_v, b_d, out_s);

    gemm3_kernel<2><<<dim3(HD / BN, BATCH / BM), 256>>>();
    epi2_kernel<<<BATCH / 8, 256>>>(h_prev, b_h, g_ln_h, b_ln_h, out_h);
}

// round 4
// speedup vs baseline: 1.1939x; 1.1939x over previous
#include <cuda_runtime.h>
#include <cuda_bf16.h>
#include <cstdint>

#define BATCH 32768
#define HD 512
typedef __nv_bfloat16 bf16;

// ---------------- device scratch (no allocations allowed) ----------------
__device__ bf16 g_x_hi[BATCH * HD];
__device__ bf16 g_x_lo[BATCH * HD];
__device__ bf16 g_u_hi[BATCH * HD];
__device__ bf16 g_u_lo[BATCH * HD];
__device__ bf16 g_t_hi[BATCH * HD];
__device__ bf16 g_t_lo[BATCH * HD];
__device__ float g_pre[BATCH * HD];               // GEMM1 out, reused for GEMM3 out
__device__ float g_P[(size_t)BATCH * 4 * HD];     // z_pre | k | v | d_pre
__device__ float g_z[BATCH * HD];
__device__ bf16 g_Wt_in_hi[HD * HD], g_Wt_in_lo[HD * HD];
__device__ bf16 g_Wt_cat_hi[4 * HD * HD], g_Wt_cat_lo[4 * HD * HD];
__device__ bf16 g_Wt_h_hi[HD * HD], g_Wt_h_lo[HD * HD];

// ---------------- helpers ----------------
__device__ __forceinline__ uint32_t smem_u32(const void* p) {
    return (uint32_t)__cvta_generic_to_shared(p);
}
__device__ __forceinline__ void cp16(uint32_t dst, const void* src) {
    asm volatile("cp.async.cg.shared.global [%0], [%1], 16;\n" :: "r"(dst), "l"(src));
}
__device__ __forceinline__ void ldm4(uint32_t (&r)[4], uint32_t addr) {
    asm volatile("ldmatrix.sync.aligned.m8n8.x4.shared.b16 {%0,%1,%2,%3}, [%4];\n"
                 : "=r"(r[0]), "=r"(r[1]), "=r"(r[2]), "=r"(r[3]) : "r"(addr));
}
__device__ __forceinline__ void mma16816(float (&d)[4], const uint32_t (&a)[4],
                                         uint32_t b0, uint32_t b1) {
    asm volatile("mma.sync.aligned.m16n8k16.row.col.f32.bf16.bf16.f32 "
                 "{%0,%1,%2,%3}, {%4,%5,%6,%7}, {%8,%9}, {%0,%1,%2,%3};\n"
                 : "+f"(d[0]), "+f"(d[1]), "+f"(d[2]), "+f"(d[3])
                 : "r"(a[0]), "r"(a[1]), "r"(a[2]), "r"(a[3]), "r"(b0), "r"(b1));
}
__device__ __forceinline__ float sigf(float x) { return 1.0f / (1.0f + __expf(-x)); }

__device__ __forceinline__ void split_store2(bf16* hi, bf16* lo, float a, float b) {
    bf16 ha = __float2bfloat16(a);
    bf16 hb = __float2bfloat16(b);
    *reinterpret_cast<__nv_bfloat162*>(hi) = __halves2bfloat162(ha, hb);
    bf16 la = __float2bfloat16(a - __bfloat162float(ha));
    bf16 lb = __float2bfloat16(b - __bfloat162float(hb));
    *reinterpret_cast<__nv_bfloat162*>(lo) = __halves2bfloat162(la, lb);
}

// ---------------- weight prep: transpose + bf16 split ----------------
__global__ void prep_weights(const float* __restrict__ W_in, const float* __restrict__ W_z,
                             const float* __restrict__ W_k, const float* __restrict__ W_v,
                             const float* __restrict__ W_d, const float* __restrict__ W_h) {
    int idx = blockIdx.x * 256 + threadIdx.x;
    if (idx >= 6 * HD * HD) return;
    int mat = idx / (HD * HD);
    int e = idx % (HD * HD);
    int k = e / HD, n = e % HD;
    const float* W;
    bf16 *hi, *lo;
    int dst;
    if (mat == 0) {
        W = W_in; hi = g_Wt_in_hi; lo = g_Wt_in_lo; dst = n * HD + k;
    } else if (mat <= 4) {
        W = (mat == 1) ? W_z : (mat == 2) ? W_k : (mat == 3) ? W_v : W_d;
        hi = g_Wt_cat_hi; lo = g_Wt_cat_lo; dst = ((mat - 1) * HD + n) * HD + k;
    } else {
        W = W_h; hi = g_Wt_h_hi; lo = g_Wt_h_lo; dst = n * HD + k;
    }
    float w = W[e];  // W[k][n], coalesced over n
    bf16 h = __float2bfloat16(w);
    hi[dst] = h;
    lo[dst] = __float2bfloat16(w - __bfloat162float(h));
}

// ---------------- split x into bf16 hi/lo ----------------
__global__ void split_x_kernel(const float* __restrict__ x) {
    int i = blockIdx.x * 256 + threadIdx.x;  // over BATCH*HD/4 float4s
    float4 v = reinterpret_cast<const float4*>(x)[i];
    size_t idx = (size_t)i * 4;
    split_store2(g_x_hi + idx, g_x_lo + idx, v.x, v.y);
    split_store2(g_x_hi + idx + 2, g_x_lo + idx + 2, v.z, v.w);
}

// ---------------- split-bf16 GEMM: C[M,N] = A[M,512] @ W[512,N] ----------------
// Fused 3-term: per k-stage load Ahi,Alo,Bhi,Blo once, compute
// Ahi*Bhi + Alo*Bhi + Ahi*Blo against the same staged data.
#define BM 128
#define BN 128
#define BK 32
#define KST 40                         // padded row stride (bf16) = 80 bytes
#define TILEB (BM * KST * 2)           // 10240 bytes per [128][40] bf16 tile
#define NSTG 16                        // 512 / 32
#define SMEM_DYN (8 * TILEB)           // 2 stages * (Ahi,Alo,Bhi,Blo) = 80 KB

template <int WHICH>
__global__ void __launch_bounds__(256, 2) gemm3_kernel() {
    const bf16* Ahi = (WHICH == 0) ? g_x_hi : (WHICH == 1) ? g_u_hi : g_t_hi;
    const bf16* Alo = (WHICH == 0) ? g_x_lo : (WHICH == 1) ? g_u_lo : g_t_lo;
    const bf16* Bhi = (WHICH == 0) ? g_Wt_in_hi : (WHICH == 1) ? g_Wt_cat_hi : g_Wt_h_hi;
    const bf16* Blo = (WHICH == 0) ? g_Wt_in_lo : (WHICH == 1) ? g_Wt_cat_lo : g_Wt_h_lo;
    float* C = (WHICH == 1) ? g_P : g_pre;
    const int N = (WHICH == 1) ? 4 * HD : HD;

    extern __shared__ __align__(16) char sm[];
    // tile(stage, sel, isB): A tiles 0..3, B tiles 4..7
    auto tileA = [&](int stage, int sel) -> bf16* {
        return reinterpret_cast<bf16*>(sm + (size_t)(stage * 2 + sel) * TILEB);
    };
    auto tileB = [&](int stage, int sel) -> bf16* {
        return reinterpret_cast<bf16*>(sm + (size_t)(4 + stage * 2 + sel) * TILEB);
    };

    const int tid = threadIdx.x;
    const int m0 = blockIdx.y * BM;
    const int n0 = blockIdx.x * BN;
    const int warp = tid >> 5, lane = tid & 31;
    const int wm = (warp >> 1) * 32;  // 4 warps along M
    const int wn = (warp & 1) * 64;   // 2 warps along N

    float acc[2][8][4];
#pragma unroll
    for (int i = 0; i < 2; i++)
#pragma unroll
        for (int j = 0; j < 8; j++)
#pragma unroll
            for (int q = 0; q < 4; q++) acc[i][j][q] = 0.f;

    // loader mapping: 512 16B-chunks per tile; thread handles 2 chunks per tile
    auto load_stage = [&](int s) {
        const int st = s & 1;
        const int k0 = s * BK;
        bf16* ah = tileA(st, 0);
        bf16* al = tileA(st, 1);
        bf16* bh = tileB(st, 0);
        bf16* bl = tileB(st, 1);
#pragma unroll
        for (int i = 0; i < 2; i++) {
            int c = i * 256 + tid;          // 0..511
            int row = c >> 2;               // 0..127
            int col = (c & 3) * 8;          // bf16 col offset within 32
            uint32_t d = (uint32_t)(row * KST + col) * 2;  // byte offset
            size_t offA = (size_t)(m0 + row) * HD + k0 + col;
            cp16(smem_u32(ah) + d, Ahi + offA);
            cp16(smem_u32(al) + d, Alo + offA);
            size_t offB = (size_t)(n0 + row) * HD + k0 + col;
            cp16(smem_u32(bh) + d, Bhi + offB);
            cp16(smem_u32(bl) + d, Blo + offB);
        }
        asm volatile("cp.async.commit_group;\n");
    };

    auto compute_pass = [&](const bf16* At, const bf16* Bt) {
#pragma unroll
        for (int kk = 0; kk < BK; kk += 16) {
            uint32_t aF[2][4];
#pragma unroll
            for (int mi = 0; mi < 2; mi++) {
                uint32_t ad = smem_u32(At + (wm + mi * 16 + (lane & 15)) * KST
                                          + kk + ((lane >> 4) << 3));
                ldm4(aF[mi], ad);
            }
            uint32_t bF[4][4];
#pragma unroll
            for (int nb = 0; nb < 4; nb++) {
                uint32_t bd = smem_u32(Bt + (wn + nb * 16 + (lane & 7) + ((lane >> 4) << 3)) * KST
                                          + kk + (((lane >> 3) & 1) << 3));
                ldm4(bF[nb], bd);
            }
#pragma unroll
            for (int mi = 0; mi < 2; mi++)
#pragma unroll
                for (int ni = 0; ni < 8; ni++)
                    mma16816(acc[mi][ni], aF[mi], bF[ni >> 1][(ni & 1) * 2],
                             bF[ni >> 1][(ni & 1) * 2 + 1]);
        }
    };

    load_stage(0);
    load_stage(1);

    for (int s = 0; s < NSTG; ++s) {
        const int st = s & 1;
        if (s == NSTG - 1) asm volatile("cp.async.wait_group 0;\n");
        else               asm volatile("cp.async.wait_group 1;\n");
        __syncthreads();
        compute_pass(tileA(st, 0), tileB(st, 0));   // Ahi * Bhi
        compute_pass(tileA(st, 1), tileB(st, 0));   // Alo * Bhi
        compute_pass(tileA(st, 0), tileB(st, 1));   // Ahi * Blo
        __syncthreads();
        if (s + 2 < NSTG) load_stage(s + 2);
    }

    // epilogue: write fp32 C
#pragma unroll
    for (int mi = 0; mi < 2; mi++)
#pragma unroll
        for (int ni = 0; ni < 8; ni++) {
            int r = m0 + wm + mi * 16 + (lane >> 2);
            int c = n0 + wn + ni * 8 + (lane & 3) * 2;
            *reinterpret_cast<float2*>(&C[(size_t)r * N + c]) =
                make_float2(acc[mi][ni][0], acc[mi][ni][1]);
            *reinterpret_cast<float2*>(&C[(size_t)(r + 8) * N + c]) =
                make_float2(acc[mi][ni][2], acc[mi][ni][3]);
        }
}

// ---------------- LN over g_pre -> u (bf16 hi/lo) ----------------
__global__ void ln_u_kernel(const float* __restrict__ bias, const float* __restrict__ gamma,
                            const float* __restrict__ beta) {
    int row = blockIdx.x * 8 + (threadIdx.x >> 5);
    int lane = threadIdx.x & 31;
    const float* p = g_pre + (size_t)row * HD;
    float v[16];
    float sm = 0.f, sq = 0.f;
#pragma unroll
    for (int i = 0; i < 4; i++) {
        int c = i * 128 + lane * 4;
        float4 x4 = *reinterpret_cast<const float4*>(p + c);
        float4 b4 = *reinterpret_cast<const float4*>(bias + c);
        float t0 = x4.x + b4.x, t1 = x4.y + b4.y, t2 = x4.z + b4.z, t3 = x4.w + b4.w;
        v[i * 4 + 0] = t0; v[i * 4 + 1] = t1; v[i * 4 + 2] = t2; v[i * 4 + 3] = t3;
        sm += t0 + t1 + t2 + t3;
        sq += t0 * t0 + t1 * t1 + t2 * t2 + t3 * t3;
    }
#pragma unroll
    for (int o = 16; o; o >>= 1) {
        sm += __shfl_xor_sync(0xffffffffu, sm, o);
        sq += __shfl_xor_sync(0xffffffffu, sq, o);
    }
    float mean = sm * (1.f / HD);
    float inv = rsqrtf(fmaxf(sq * (1.f / HD) - mean * mean, 0.f) + 1e-5f);
#pragma unroll
    for (int i = 0; i < 4; i++) {
        int c = i * 128 + lane * 4;
        float4 g4 = *reinterpret_cast<const float4*>(gamma + c);
        float4 b4 = *reinterpret_cast<const float4*>(beta + c);
        float u0 = (v[i * 4 + 0] - mean) * inv * g4.x + b4.x;
        float u1 = (v[i * 4 + 1] - mean) * inv * g4.y + b4.y;
        float u2 = (v[i * 4 + 2] - mean) * inv * g4.z + b4.z;
        float u3 = (v[i * 4 + 3] - mean) * inv * g4.w + b4.w;
        size_t idx = (size_t)row * HD + c;
        split_store2(g_u_hi + idx, g_u_lo + idx, u0, u1);
        split_store2(g_u_hi + idx + 2, g_u_lo + idx + 2, u2, u3);
    }
}

// ---------------- epilogue 1: z, s, t ----------------
__global__ void epi1_kernel(const float* __restrict__ s_prev, const float* __restrict__ bz,
                            const float* __restrict__ glz, const float* __restrict__ blz,
                            const float* __restrict__ bk, const float* __restrict__ bv,
                            const float* __restrict__ bd, float* __restrict__ out_s) {
    int row = blockIdx.x * 8 + (threadIdx.x >> 5);
    int lane = threadIdx.x & 31;
    const float* Pr = g_P + (size_t)row * (4 * HD);
    float zp[16];
    float sm = 0.f, sq = 0.f;
#pragma unroll
    for (int i = 0; i < 4; i++) {
        int c = i * 128 + lane * 4;
        float4 z4 = *reinterpret_cast<const float4*>(Pr + c);
        float4 b4 = *reinterpret_cast<const float4*>(bz + c);
        float t0 = z4.x + b4.x, t1 = z4.y + b4.y, t2 = z4.z + b4.z, t3 = z4.w + b4.w;
        zp[i * 4 + 0] = t0; zp[i * 4 + 1] = t1; zp[i * 4 + 2] = t2; zp[i * 4 + 3] = t3;
        sm += t0 + t1 + t2 + t3;
        sq += t0 * t0 + t1 * t1 + t2 * t2 + t3 * t3;
    }
#pragma unroll
    for (int o = 16; o; o >>= 1) {
        sm += __shfl_xor_sync(0xffffffffu, sm, o);
        sq += __shfl_xor_sync(0xffffffffu, sq, o);
    }
    float mean = sm * (1.f / HD);
    float inv = rsqrtf(fmaxf(sq * (1.f / HD) - mean * mean, 0.f) + 1e-5f);
#pragma unroll
    for (int i = 0; i < 4; i++) {
        int c = i * 128 + lane * 4;
        size_t idx = (size_t)row * HD + c;
        float4 g4 = *reinterpret_cast<const float4*>(glz + c);
        float4 bb4 = *reinterpret_cast<const float4*>(blz + c);
        float z0 = sigf((zp[i * 4 + 0] - mean) * inv * g4.x + bb4.x);
        float z1 = sigf((zp[i * 4 + 1] - mean) * inv * g4.y + bb4.y);
        float z2 = sigf((zp[i * 4 + 2] - mean) * inv * g4.z + bb4.z);
        float z3 = sigf((zp[i * 4 + 3] - mean) * inv * g4.w + bb4.w);

        float4 k4 = *reinterpret_cast<const float4*>(Pr + HD + c);
        float4 bk4 = *reinterpret_cast<const float4*>(bk + c);
        float4 v4 = *reinterpret_cast<const float4*>(Pr + 2 * HD + c);
        float4 bv4 = *reinterpret_cast<const float4*>(bv + c);
        float4 d4 = *reinterpret_cast<const float4*>(Pr + 3 * HD + c);
        float4 bd4 = *reinterpret_cast<const float4*>(bd + c);
        float4 sp = *reinterpret_cast<const float4*>(s_prev + idx);

        float kk0 = k4.x + bk4.x, kk1 = k4.y + bk4.y, kk2 = k4.z + bk4.z, kk3 = k4.w + bk4.w;
        float vv0 = v4.x + bv4.x, vv1 = v4.y + bv4.y, vv2 = v4.z + bv4.z, vv3 = v4.w + bv4.w;
        float dc0 = sigf(d4.x + bd4.x), dc1 = sigf(d4.y + bd4.y);
        float dc2 = sigf(d4.z + bd4.z), dc3 = sigf(d4.w + bd4.w);
        float s0 = dc0 * sp.x + kk0 * vv0;
        float s1 = dc1 * sp.y + kk1 * vv1;
        float s2 = dc2 * sp.z + kk2 * vv2;
        float s3 = dc3 * sp.w + kk3 * vv3;
        *reinterpret_cast<float4*>(out_s + idx) = make_float4(s0, s1, s2, s3);

        __nv_bfloat162 uh0 = *reinterpret_cast<const __nv_bfloat162*>(g_u_hi + idx);
        __nv_bfloat162 ul0 = *reinterpret_cast<const __nv_bfloat162*>(g_u_lo + idx);
        __nv_bfloat162 uh1 = *reinterpret_cast<const __nv_bfloat162*>(g_u_hi + idx + 2);
        __nv_bfloat162 ul1 = *reinterpret_cast<const __nv_bfloat162*>(g_u_lo + idx + 2);
        float u0 = __bfloat162float(uh0.x) + __bfloat162float(ul0.x);
        float u1 = __bfloat162float(uh0.y) + __bfloat162float(ul0.y);
        float u2 = __bfloat162float(uh1.x) + __bfloat162float(ul1.x);
        float u3 = __bfloat162float(uh1.y) + __bfloat162float(ul1.y);
        split_store2(g_t_hi + idx, g_t_lo + idx, u0 + s0, u1 + s1);
        split_store2(g_t_hi + idx + 2, g_t_lo + idx + 2, u2 + s2, u3 + s3);
        *reinterpret_cast<float4*>(g_z + idx) = make_float4(z0, z1, z2, z3);
    }
}

// ---------------- epilogue 2: h ----------------
__global__ void epi2_kernel(const float* __restrict__ h_prev, const float* __restrict__ bh,
                            const float* __restrict__ glh, const float* __restrict__ blh,
                            float* __restrict__ out_h) {
    int row = blockIdx.x * 8 + (threadIdx.x >> 5);
    int lane = threadIdx.x & 31;
    const float* p = g_pre + (size_t)row * HD;
    float v[16];
    float sm = 0.f, sq = 0.f;
#pragma unroll
    for (int i = 0; i < 4; i++) {
        int c = i * 128 + lane * 4;
        float4 x4 = *reinterpret_cast<const float4*>(p + c);
        float4 b4 = *reinterpret_cast<const float4*>(bh + c);
        float t0 = x4.x + b4.x, t1 = x4.y + b4.y, t2 = x4.z + b4.z, t3 = x4.w + b4.w;
        v[i * 4 + 0] = t0; v[i * 4 + 1] = t1; v[i * 4 + 2] = t2; v[i * 4 + 3] = t3;
        sm += t0 + t1 + t2 + t3;
        sq += t0 * t0 + t1 * t1 + t2 * t2 + t3 * t3;
    }
#pragma unroll
    for (int o = 16; o; o >>= 1) {
        sm += __shfl_xor_sync(0xffffffffu, sm, o);
        sq += __shfl_xor_sync(0xffffffffu, sq, o);
    }
    float mean = sm * (1.f / HD);
    float inv = rsqrtf(fmaxf(sq * (1.f / HD) - mean * mean, 0.f) + 1e-5f);
#pragma unroll
    for (int i = 0; i < 4; i++) {
        int c = i * 128 + lane * 4;
        size_t idx = (size_t)row * HD + c;
        float4 g4 = *reinterpret_cast<const float4*>(glh + c);
        float4 b4 = *reinterpret_cast<const float4*>(blh + c);
        float c0 = tanhf((v[i * 4 + 0] - mean) * inv * g4.x + b4.x);
        float c1 = tanhf((v[i * 4 + 1] - mean) * inv * g4.y + b4.y);
        float c2 = tanhf((v[i * 4 + 2] - mean) * inv * g4.z + b4.z);
        float c3 = tanhf((v[i * 4 + 3] - mean) * inv * g4.w + b4.w);
        float4 z4 = *reinterpret_cast<const float4*>(g_z + idx);
        float4 hp = *reinterpret_cast<const float4*>(h_prev + idx);
        float h0 = (1.f - z4.x) * c0 + z4.x * hp.x;
        float h1 = (1.f - z4.y) * c1 + z4.y * hp.y;
        float h2 = (1.f - z4.z) * c2 + z4.z * hp.z;
        float h3 = (1.f - z4.w) * c3 + z4.w * hp.w;
        *reinterpret_cast<float4*>(out_h + idx) = make_float4(h0, h1, h2, h3);
    }
}

// ---------------- launch ----------------
extern "C" void kernel_launch(void* const* d_in, const int* in_sizes, int n_in,
                              void* d_out, int out_size) {
    const float* x       = (const float*)d_in[0];
    const float* h_prev  = (const float*)d_in[1];
    const float* s_prev  = (const float*)d_in[2];
    const float* W_in    = (const float*)d_in[3];
    const float* b_in    = (const float*)d_in[4];
    const float* g_ln_in = (const float*)d_in[5];
    const float* b_ln_in = (const float*)d_in[6];
    const float* g_ln_z  = (const float*)d_in[9];
    const float* b_ln_z  = (const float*)d_in[10];
    const float* g_ln_h  = (const float*)d_in[11];
    const float* b_ln_h  = (const float*)d_in[12];
    const float* W_z     = (const float*)d_in[15];
    const float* b_z     = (const float*)d_in[16];
    const float* W_k     = (const float*)d_in[17];
    const float* b_k     = (const float*)d_in[18];
    const float* W_v     = (const float*)d_in[19];
    const float* b_v     = (const float*)d_in[20];
    const float* W_h     = (const float*)d_in[21];
    const float* b_h     = (const float*)d_in[22];
    const float* W_d     = (const float*)d_in[23];
    const float* b_d     = (const float*)d_in[24];

    float* out_h = (float*)d_out;
    float* out_s = out_h + (size_t)BATCH * HD;

    cudaFuncSetAttribute(gemm3_kernel<0>, cudaFuncAttributeMaxDynamicSharedMemorySize, SMEM_DYN);
    cudaFuncSetAttribute(gemm3_kernel<1>, cudaFuncAttributeMaxDynamicSharedMemorySize, SMEM_DYN);
    cudaFuncSetAttribute(gemm3_kernel<2>, cudaFuncAttributeMaxDynamicSharedMemorySize, SMEM_DYN);

    prep_weights<<<(6 * HD * HD + 255) / 256, 256>>>(W_in, W_z, W_k, W_v, W_d, W_h);
    split_x_kernel<<<BATCH * HD / 4 / 256, 256>>>(x);

    gemm3_kernel<0><<<dim3(HD / BN, BATCH / BM), 256, SMEM_DYN>>>();
    ln_u_kernel<<<BATCH / 8, 256>>>(b_in, g_ln_in, b_ln_in);

    gemm3_kernel<1><<<dim3(4 * HD / BN, BATCH / BM), 256, SMEM_DYN>>>();
    epi1_kernel<<<BATCH / 8, 256>>>(s_prev, b_z, g_ln_z, b_ln_z, b_k, b_v, b_d, out_s);

    gemm3_kernel<2><<<dim3(HD / BN, BATCH / BM), 256, SMEM_DYN>>>();
    epi2_kernel<<<BATCH / 8, 256>>>(h_prev, b_h, g_ln_h, b_ln_h, out_h);
}